// round 4
// baseline (speedup 1.0000x reference)
#include <cuda_runtime.h>
#include <cuda_bf16.h>
#include <cstdint>

// YOLOv1 loss — persistent blocks + 3-stage cp.async.bulk ring pipeline.
// Tile = 128 cells (15360 B per array, 30720 B per stage). At iteration it a
// block waits stage it%3, computes, and has already issued tile it+2 into
// stage (it+2)%3 — keeping up to two tile-pairs (61 KB) in flight per block
// at all times. 2 blocks/SM (92 KB dyn SMEM each).
// Deterministic: fixed tile order per block (double acc), last block folds
// partials in fixed index order; arrival counter reset every launch.

#define CPB 128                       // cells per tile == threads per block
#define CH 30
#define TILE_FLOATS (CPB * CH)        // 3840
#define TILE_BYTES  (TILE_FLOATS * 4) // 15360
#define STAGE_FLOATS (2 * TILE_FLOATS)
#define STAGE_BYTES (2 * TILE_BYTES)  // 30720 (p + t)
#define NSTAGE 3
#define MAXG 4096

static __device__ double g_partials[MAXG];
static __device__ unsigned int g_arrived;

__device__ __forceinline__ uint32_t smem_u32(const void* p) {
    uint32_t a;
    asm("{ .reg .u64 t; cvta.to.shared.u64 t, %1; cvt.u32.u64 %0, t; }"
        : "=r"(a) : "l"(p));
    return a;
}

__device__ __forceinline__ void mbar_init(uint32_t mb, uint32_t cnt) {
    asm volatile("mbarrier.init.shared.b64 [%0], %1;" :: "r"(mb), "r"(cnt) : "memory");
}

__device__ __forceinline__ void mbar_expect_tx(uint32_t mb, uint32_t bytes) {
    asm volatile("mbarrier.arrive.expect_tx.shared.b64 _, [%0], %1;"
                 :: "r"(mb), "r"(bytes) : "memory");
}

__device__ __forceinline__ void bulk_g2s(uint32_t dst, const void* src,
                                         uint32_t bytes, uint32_t mb) {
    asm volatile(
        "cp.async.bulk.shared::cluster.global.mbarrier::complete_tx::bytes "
        "[%0], [%1], %2, [%3];"
        :: "r"(dst), "l"(src), "r"(bytes), "r"(mb) : "memory");
}

__device__ __forceinline__ void mbar_wait(uint32_t mb, uint32_t parity) {
    uint32_t done = 0;
    while (!done) {
        asm volatile(
            "{\n\t.reg .pred p;\n\t"
            "mbarrier.try_wait.parity.shared.b64 p, [%1], %2, 0x989680;\n\t"
            "selp.b32 %0, 1, 0, p;\n\t}"
            : "=r"(done) : "r"(mb), "r"(parity) : "memory");
    }
}

__device__ __forceinline__ float iou_f(float ax1, float ay1, float ax2, float ay2,
                                       float bx1, float by1, float bx2, float by2) {
    float xl = fmaxf(ax1, bx1);
    float yt = fmaxf(ay1, by1);
    float xr = fminf(ax2, bx2);
    float yb = fminf(ay2, by2);
    float ix = fmaxf(xr - xl, 0.0f);
    float iy = fmaxf(yb - yt, 0.0f);
    float inter = ix * iy;
    float aa = fabsf((ax2 - ax1) * (ay2 - ay1));
    float ba = fabsf((bx2 - bx1) * (by2 - by1));
    return inter / (aa + ba - inter + 1e-7f);
}

__device__ __forceinline__ float sgn_sqrt(float x) {
    float s = sqrtf(fabsf(x));
    return (x > 0.0f) ? s : ((x < 0.0f) ? -s : 0.0f);
}

// Loss for one cell. p, t: 30 floats each. rc = cell % 49.
__device__ __forceinline__ float cell_loss(const float* __restrict__ p,
                                           const float* __restrict__ t, int rc) {
    const float lty = (float)(rc / 7) * (1.0f / 7.0f);
    const float ltx = (float)(rc % 7) * (1.0f / 7.0f);

    const float t4 = t[4];
    const float coordf = (t4 > 0.0f) ? 1.0f : 0.0f;
    const float noobjf = (t4 == 0.0f) ? 1.0f : 0.0f;

    float b1x1 = ltx + p[0] * (1.0f / 7.0f) - p[2] * 0.5f;
    float b1y1 = lty + p[1] * (1.0f / 7.0f) - p[3] * 0.5f;
    float b1x2 = p[2] + b1x1;
    float b1y2 = p[3] + b1y1;
    const float c2 = (1.0f / 7.0f) - 0.5f;   // faithful to reference bug
    float b2x1 = ltx + p[5] * c2;
    float b2y1 = lty + p[6] * c2;
    float b2x2 = p[7] + b2x1;
    float b2y2 = p[8] + b2y1;
    float tbx1 = ltx + t[0] * (1.0f / 7.0f) - t[2] * 0.5f;
    float tby1 = lty + t[1] * (1.0f / 7.0f) - t[3] * 0.5f;
    float tbx2 = t[2] + tbx1;
    float tby2 = t[3] + tby1;

    float iou1 = iou_f(b1x1, b1y1, b1x2, b1y2, tbx1, tby1, tbx2, tby2);
    float iou2 = iou_f(b2x1, b2y1, b2x2, b2y2, tbx1, tby1, tbx2, tby2);
    bool sel = (iou1 >= iou2);

    float bx0 = sel ? p[0] : p[5];
    float bx1 = sel ? p[1] : p[6];
    float bx2 = sel ? p[2] : p[7];
    float bx3 = sel ? p[3] : p[8];
    float bx4 = sel ? p[4] : p[9];

    float dx = bx0 - t[0];
    float dy = bx1 - t[1];
    float lxy = dx * dx + dy * dy;

    float dw = sgn_sqrt(bx2) - sqrtf(t[2]);
    float dh = sgn_sqrt(bx3) - sqrtf(t[3]);
    float lwh = dw * dw + dh * dh;

    float dob = fmaxf(iou1, iou2) - bx4;
    float lobj = dob * dob;

    float dn1 = p[4] - t[4];
    float dn2 = p[9] - t[9];
    float lnoobj = dn1 * dn1 + dn2 * dn2;

    float llab = 0.0f;
    #pragma unroll
    for (int k = 10; k < 30; k++) {
        float d = p[k] - t[k];
        llab += d * d;
    }

    return coordf * (5.0f * (lxy + lwh) + lobj + llab) + 0.5f * noobjf * lnoobj;
}

__global__ void __launch_bounds__(CPB, 2)
yolo_loss_pipe3(const float* __restrict__ p_g, const float* __restrict__ t_g,
                float* __restrict__ out, int totalCells, float inv_batch,
                int nFull) {
    extern __shared__ float smem[];  // [NSTAGE][STAGE_FLOATS]: p then t per stage

    __shared__ __align__(8) uint64_t mbar_store[NSTAGE];
    __shared__ double warp_s[CPB / 32];
    __shared__ int s_is_last;

    const int tid = threadIdx.x;
    const int B = gridDim.x;
    uint32_t mb[NSTAGE];
    #pragma unroll
    for (int s = 0; s < NSTAGE; s++) mb[s] = smem_u32(&mbar_store[s]);
    const uint32_t smem_a = smem_u32(smem);

    if (tid == 0) {
        #pragma unroll
        for (int s = 0; s < NSTAGE; s++) mbar_init(mb[s], 1);
    }
    __syncthreads();

    // prologue: prefetch tiles for iterations 0..NSTAGE-2 into stages 0..NSTAGE-2
    if (tid == 0) {
        #pragma unroll
        for (int s = 0; s < NSTAGE - 1; s++) {
            const int tile = (int)blockIdx.x + s * B;
            if (tile < nFull) {
                const uint32_t st_a = smem_a + s * STAGE_BYTES;
                mbar_expect_tx(mb[s], STAGE_BYTES);
                bulk_g2s(st_a, p_g + (size_t)tile * TILE_FLOATS, TILE_BYTES, mb[s]);
                bulk_g2s(st_a + TILE_BYTES, t_g + (size_t)tile * TILE_FLOATS,
                         TILE_BYTES, mb[s]);
            }
        }
    }

    double acc = 0.0;
    uint32_t ph[NSTAGE] = {0, 0, 0};
    int st = 0;        // stage of current iteration
    int st_iss = NSTAGE - 1;  // stage to issue into (= (it + NSTAGE-1) % NSTAGE)
    int it = 0;
    for (int tile = blockIdx.x; tile < nFull; tile += B, it++) {
        // issue tile (it + NSTAGE-1) into stage st_iss (consumed NSTAGE-1 iters ago)
        const int nxt = tile + (NSTAGE - 1) * B;
        if (tid == 0 && nxt < nFull) {
            const uint32_t st_a = smem_a + st_iss * STAGE_BYTES;
            mbar_expect_tx(mb[st_iss], STAGE_BYTES);
            bulk_g2s(st_a, p_g + (size_t)nxt * TILE_FLOATS, TILE_BYTES, mb[st_iss]);
            bulk_g2s(st_a + TILE_BYTES, t_g + (size_t)nxt * TILE_FLOATS,
                     TILE_BYTES, mb[st_iss]);
        }

        // wait current stage
        mbar_wait(mb[st], ph[st]);
        ph[st] ^= 1;

        const float* p = smem + st * STAGE_FLOATS + tid * CH;
        const float* t = p + TILE_FLOATS;
        const int cell = tile * CPB + tid;
        acc += (double)cell_loss(p, t, cell % 49);

        __syncthreads();  // stage consumed by all warps -> free for reissue

        st = (st + 1 == NSTAGE) ? 0 : st + 1;
        st_iss = (st_iss + 1 == NSTAGE) ? 0 : st_iss + 1;
    }

    // tail tile (ragged), handled by the block that would own tile nFull
    if (nFull * CPB < totalCells && (nFull % B) == (int)blockIdx.x) {
        const int cell = nFull * CPB + tid;
        if (cell < totalCells) {
            float pl[CH], tl[CH];
            #pragma unroll
            for (int k = 0; k < CH; k++) {
                pl[k] = p_g[(size_t)cell * CH + k];
                tl[k] = t_g[(size_t)cell * CH + k];
            }
            acc += (double)cell_loss(pl, tl, cell % 49);
        }
    }

    // deterministic block reduction (double)
    #pragma unroll
    for (int o = 16; o > 0; o >>= 1)
        acc += __shfl_down_sync(0xFFFFFFFFu, acc, o);
    if ((tid & 31) == 0) warp_s[tid >> 5] = acc;
    __syncthreads();
    if (tid == 0) {
        double v = warp_s[0] + warp_s[1] + warp_s[2] + warp_s[3];
        g_partials[blockIdx.x] = v;
        __threadfence();
        unsigned int old = atomicAdd(&g_arrived, 1u);
        s_is_last = (old == gridDim.x - 1) ? 1 : 0;
    }
    __syncthreads();

    if (s_is_last) {
        const int nparts = gridDim.x;
        double v = 0.0;
        for (int i = tid; i < nparts; i += CPB)
            v += g_partials[i];
        #pragma unroll
        for (int o = 16; o > 0; o >>= 1)
            v += __shfl_down_sync(0xFFFFFFFFu, v, o);
        if ((tid & 31) == 0) warp_s[tid >> 5] = v;
        __syncthreads();
        if (tid == 0) {
            double w = warp_s[0] + warp_s[1] + warp_s[2] + warp_s[3];
            out[0] = (float)(w * (double)inv_batch);
            g_arrived = 0;  // reset for next launch / graph replay
        }
    }
}

extern "C" void kernel_launch(void* const* d_in, const int* in_sizes, int n_in,
                              void* d_out, int out_size) {
    const float* p = (const float*)d_in[0];  // modely [N,7,7,30]
    const float* t = (const float*)d_in[1];  // targety [N,7,7,30]
    float* out = (float*)d_out;

    const int totalCells = in_sizes[0] / CH;  // N*49
    const int nbatch = totalCells / 49;       // N
    const int nFull = totalCells / CPB;
    const int totalTiles = (totalCells + CPB - 1) / CPB;

    int nblocks = 148 * 2;                    // 2 resident blocks/SM (92 KB SMEM each)
    if (nblocks > totalTiles) nblocks = totalTiles;
    if (nblocks < 1) nblocks = 1;
    if (nblocks > MAXG) nblocks = MAXG;

    const int smem_bytes = NSTAGE * STAGE_BYTES;  // 92160
    static bool attr_set = false;
    if (!attr_set) {
        cudaFuncSetAttribute(yolo_loss_pipe3,
                             cudaFuncAttributeMaxDynamicSharedMemorySize,
                             smem_bytes);
        attr_set = true;
    }

    yolo_loss_pipe3<<<nblocks, CPB, smem_bytes>>>(p, t, out, totalCells,
                                                  1.0f / (float)nbatch, nFull);
}

// round 6
// speedup vs baseline: 1.2330x; 1.2330x over previous
#include <cuda_runtime.h>
#include <cuda_bf16.h>
#include <cstdint>

// YOLOv1 loss — persistent blocks + double-buffered cp.async.bulk pipeline.
// R6 (= R5 resubmit; prior round was an infra failure): the 16.9us R3 config
// (2 stages, 128-cell tiles, 3 blocks/SM) with a load-balanced grid: B chosen
// so every block runs the SAME tile count (3136 tiles -> 392 blocks x 8
// tiles), removing the ~14% drain tail.
// Deterministic: fixed tile order per block (double acc); last block folds
// partials in fixed index order; arrival counter reset every launch.

#define CPB 128                       // cells per tile == threads per block
#define CH 30
#define TILE_FLOATS (CPB * CH)        // 3840
#define TILE_BYTES  (TILE_FLOATS * 4) // 15360
#define STAGE_BYTES (2 * TILE_BYTES)  // 30720 (p + t)
#define MAXG 4096

static __device__ double g_partials[MAXG];
static __device__ unsigned int g_arrived;

__device__ __forceinline__ uint32_t smem_u32(const void* p) {
    uint32_t a;
    asm("{ .reg .u64 t; cvta.to.shared.u64 t, %1; cvt.u32.u64 %0, t; }"
        : "=r"(a) : "l"(p));
    return a;
}

__device__ __forceinline__ void mbar_init(uint32_t mb, uint32_t cnt) {
    asm volatile("mbarrier.init.shared.b64 [%0], %1;" :: "r"(mb), "r"(cnt) : "memory");
}

__device__ __forceinline__ void mbar_expect_tx(uint32_t mb, uint32_t bytes) {
    asm volatile("mbarrier.arrive.expect_tx.shared.b64 _, [%0], %1;"
                 :: "r"(mb), "r"(bytes) : "memory");
}

__device__ __forceinline__ void bulk_g2s(uint32_t dst, const void* src,
                                         uint32_t bytes, uint32_t mb) {
    asm volatile(
        "cp.async.bulk.shared::cluster.global.mbarrier::complete_tx::bytes "
        "[%0], [%1], %2, [%3];"
        :: "r"(dst), "l"(src), "r"(bytes), "r"(mb) : "memory");
}

__device__ __forceinline__ void mbar_wait(uint32_t mb, uint32_t parity) {
    uint32_t done = 0;
    while (!done) {
        asm volatile(
            "{\n\t.reg .pred p;\n\t"
            "mbarrier.try_wait.parity.shared.b64 p, [%1], %2, 0x989680;\n\t"
            "selp.b32 %0, 1, 0, p;\n\t}"
            : "=r"(done) : "r"(mb), "r"(parity) : "memory");
    }
}

__device__ __forceinline__ float iou_f(float ax1, float ay1, float ax2, float ay2,
                                       float bx1, float by1, float bx2, float by2) {
    float xl = fmaxf(ax1, bx1);
    float yt = fmaxf(ay1, by1);
    float xr = fminf(ax2, bx2);
    float yb = fminf(ay2, by2);
    float ix = fmaxf(xr - xl, 0.0f);
    float iy = fmaxf(yb - yt, 0.0f);
    float inter = ix * iy;
    float aa = fabsf((ax2 - ax1) * (ay2 - ay1));
    float ba = fabsf((bx2 - bx1) * (by2 - by1));
    return inter / (aa + ba - inter + 1e-7f);
}

__device__ __forceinline__ float sgn_sqrt(float x) {
    float s = sqrtf(fabsf(x));
    return (x > 0.0f) ? s : ((x < 0.0f) ? -s : 0.0f);
}

// Loss for one cell. p, t: 30 floats each. rc = cell % 49.
__device__ __forceinline__ float cell_loss(const float* __restrict__ p,
                                           const float* __restrict__ t, int rc) {
    const float lty = (float)(rc / 7) * (1.0f / 7.0f);
    const float ltx = (float)(rc % 7) * (1.0f / 7.0f);

    const float t4 = t[4];
    const float coordf = (t4 > 0.0f) ? 1.0f : 0.0f;
    const float noobjf = (t4 == 0.0f) ? 1.0f : 0.0f;

    float b1x1 = ltx + p[0] * (1.0f / 7.0f) - p[2] * 0.5f;
    float b1y1 = lty + p[1] * (1.0f / 7.0f) - p[3] * 0.5f;
    float b1x2 = p[2] + b1x1;
    float b1y2 = p[3] + b1y1;
    const float c2 = (1.0f / 7.0f) - 0.5f;   // faithful to reference bug
    float b2x1 = ltx + p[5] * c2;
    float b2y1 = lty + p[6] * c2;
    float b2x2 = p[7] + b2x1;
    float b2y2 = p[8] + b2y1;
    float tbx1 = ltx + t[0] * (1.0f / 7.0f) - t[2] * 0.5f;
    float tby1 = lty + t[1] * (1.0f / 7.0f) - t[3] * 0.5f;
    float tbx2 = t[2] + tbx1;
    float tby2 = t[3] + tby1;

    float iou1 = iou_f(b1x1, b1y1, b1x2, b1y2, tbx1, tby1, tbx2, tby2);
    float iou2 = iou_f(b2x1, b2y1, b2x2, b2y2, tbx1, tby1, tbx2, tby2);
    bool sel = (iou1 >= iou2);

    float bx0 = sel ? p[0] : p[5];
    float bx1 = sel ? p[1] : p[6];
    float bx2 = sel ? p[2] : p[7];
    float bx3 = sel ? p[3] : p[8];
    float bx4 = sel ? p[4] : p[9];

    float dx = bx0 - t[0];
    float dy = bx1 - t[1];
    float lxy = dx * dx + dy * dy;

    float dw = sgn_sqrt(bx2) - sqrtf(t[2]);
    float dh = sgn_sqrt(bx3) - sqrtf(t[3]);
    float lwh = dw * dw + dh * dh;

    float dob = fmaxf(iou1, iou2) - bx4;
    float lobj = dob * dob;

    float dn1 = p[4] - t[4];
    float dn2 = p[9] - t[9];
    float lnoobj = dn1 * dn1 + dn2 * dn2;

    float llab = 0.0f;
    #pragma unroll
    for (int k = 10; k < 30; k++) {
        float d = p[k] - t[k];
        llab += d * d;
    }

    return coordf * (5.0f * (lxy + lwh) + lobj + llab) + 0.5f * noobjf * lnoobj;
}

__global__ void __launch_bounds__(CPB, 3)
yolo_loss_pipe(const float* __restrict__ p_g, const float* __restrict__ t_g,
               float* __restrict__ out, int totalCells, float inv_batch,
               int nFull) {
    extern __shared__ float smem[];
    float* pbuf = smem;                      // [2][TILE_FLOATS]
    float* tbuf = smem + 2 * TILE_FLOATS;    // [2][TILE_FLOATS]

    __shared__ __align__(8) uint64_t mbar_store[2];
    __shared__ double warp_s[CPB / 32];
    __shared__ int s_is_last;

    const int tid = threadIdx.x;
    const int B = gridDim.x;
    const uint32_t mb0 = smem_u32(&mbar_store[0]);
    const uint32_t mb1 = smem_u32(&mbar_store[1]);
    const uint32_t pbuf_a = smem_u32(pbuf);
    const uint32_t tbuf_a = smem_u32(tbuf);

    if (tid == 0) { mbar_init(mb0, 1); mbar_init(mb1, 1); }
    __syncthreads();

    // prologue: prefetch first tile into stage 0
    if (tid == 0 && (int)blockIdx.x < nFull) {
        mbar_expect_tx(mb0, STAGE_BYTES);
        bulk_g2s(pbuf_a, p_g + (size_t)blockIdx.x * TILE_FLOATS, TILE_BYTES, mb0);
        bulk_g2s(tbuf_a, t_g + (size_t)blockIdx.x * TILE_FLOATS, TILE_BYTES, mb0);
    }

    double acc = 0.0;
    uint32_t ph0 = 0, ph1 = 0;
    int it = 0;
    for (int tile = blockIdx.x; tile < nFull; tile += B, it++) {
        const int st = it & 1;
        const uint32_t mb = st ? mb1 : mb0;

        // issue next tile into the other stage (freed by last iter's barrier)
        const int nxt = tile + B;
        if (tid == 0 && nxt < nFull) {
            const uint32_t mbn = st ? mb0 : mb1;
            const uint32_t off = (uint32_t)(st ^ 1) * TILE_BYTES;
            mbar_expect_tx(mbn, STAGE_BYTES);
            bulk_g2s(pbuf_a + off, p_g + (size_t)nxt * TILE_FLOATS, TILE_BYTES, mbn);
            bulk_g2s(tbuf_a + off, t_g + (size_t)nxt * TILE_FLOATS, TILE_BYTES, mbn);
        }

        // wait current stage
        if (st) { mbar_wait(mb, ph1); ph1 ^= 1; }
        else    { mbar_wait(mb, ph0); ph0 ^= 1; }

        const float* p = pbuf + st * TILE_FLOATS + tid * CH;
        const float* t = tbuf + st * TILE_FLOATS + tid * CH;
        const int cell = tile * CPB + tid;
        acc += (double)cell_loss(p, t, cell % 49);

        __syncthreads();  // stage free for reuse
    }

    // tail tile (ragged) — dead for N=8192 (401408 % 128 == 0), kept for safety
    if (nFull * CPB < totalCells && (nFull % B) == (int)blockIdx.x) {
        const int cell = nFull * CPB + tid;
        if (cell < totalCells) {
            float pl[CH], tl[CH];
            #pragma unroll
            for (int k = 0; k < CH; k++) {
                pl[k] = p_g[(size_t)cell * CH + k];
                tl[k] = t_g[(size_t)cell * CH + k];
            }
            acc += (double)cell_loss(pl, tl, cell % 49);
        }
    }

    // deterministic block reduction (double)
    #pragma unroll
    for (int o = 16; o > 0; o >>= 1)
        acc += __shfl_down_sync(0xFFFFFFFFu, acc, o);
    if ((tid & 31) == 0) warp_s[tid >> 5] = acc;
    __syncthreads();
    if (tid == 0) {
        double v = warp_s[0] + warp_s[1] + warp_s[2] + warp_s[3];
        g_partials[blockIdx.x] = v;
        __threadfence();
        unsigned int old = atomicAdd(&g_arrived, 1u);
        s_is_last = (old == gridDim.x - 1) ? 1 : 0;
    }
    __syncthreads();

    if (s_is_last) {
        const int nparts = gridDim.x;
        double v = 0.0;
        for (int i = tid; i < nparts; i += CPB)
            v += g_partials[i];
        #pragma unroll
        for (int o = 16; o > 0; o >>= 1)
            v += __shfl_down_sync(0xFFFFFFFFu, v, o);
        if ((tid & 31) == 0) warp_s[tid >> 5] = v;
        __syncthreads();
        if (tid == 0) {
            double w = warp_s[0] + warp_s[1] + warp_s[2] + warp_s[3];
            out[0] = (float)(w * (double)inv_batch);
            g_arrived = 0;  // reset for next launch / graph replay
        }
    }
}

extern "C" void kernel_launch(void* const* d_in, const int* in_sizes, int n_in,
                              void* d_out, int out_size) {
    const float* p = (const float*)d_in[0];  // modely [N,7,7,30]
    const float* t = (const float*)d_in[1];  // targety [N,7,7,30]
    float* out = (float*)d_out;

    const int totalCells = in_sizes[0] / CH;  // N*49 = 401408
    const int nbatch = totalCells / 49;       // N
    const int nFull = totalCells / CPB;       // 3136
    const int totalTiles = (totalCells + CPB - 1) / CPB;

    // Load-balanced grid: capacity = 3 blocks/SM x 148 SMs = 444.
    // Pick B = ceil(nFull / ceil(nFull/cap)) so tiles/block is uniform
    // (3136 -> iters=8 -> B=392: every block runs exactly 8 tiles).
    const int cap = 148 * 3;
    int nblocks;
    if (totalTiles <= cap) {
        nblocks = totalTiles;
    } else {
        const int iters = (nFull + cap - 1) / cap;
        nblocks = (nFull + iters - 1) / iters;
    }
    if (nblocks < 1) nblocks = 1;
    if (nblocks > MAXG) nblocks = MAXG;

    const int smem_bytes = 2 * STAGE_BYTES;  // 61440
    static bool attr_set = false;
    if (!attr_set) {
        cudaFuncSetAttribute(yolo_loss_pipe,
                             cudaFuncAttributeMaxDynamicSharedMemorySize,
                             smem_bytes);
        attr_set = true;
    }

    yolo_loss_pipe<<<nblocks, CPB, smem_bytes>>>(p, t, out, totalCells,
                                                 1.0f / (float)nbatch, nFull);
}